// round 3
// baseline (speedup 1.0000x reference)
#include <cuda_runtime.h>
#include <math.h>
#include <stdint.h>

// Problem constants
#define Bq 8
#define Nq 2048
#define Cq 384
#define Hq 6
#define Dq 64
#define Mq (Bq * Nq)      // 16384 tokens
#define QKVq (3 * Cq)     // 1152
#define BHq (Bq * Hq)     // 48

// smem strides (words), chosen for bank-conflict-free fragment access
#define SSTR 2052   // scores strip stride: 2052%32=4 -> a-frag rows hit distinct banks
#define QSTR 65
#define KSTR 68     // 68%32=4 -> b-frag keys hit distinct banks

// Scratch (device globals: no allocation allowed)
__device__ float g_q[BHq * Nq * Dq];
__device__ float g_k[BHq * Nq * Dq];
__device__ float g_v[BHq * Nq * Dq];
__device__ float g_ctx[(size_t)Mq * Cq];

// ---------------------------------------------------------------------------
// tf32 helpers
// ---------------------------------------------------------------------------
__device__ __forceinline__ uint32_t f2tf(float x) {
    uint32_t r;
    asm("cvt.rna.tf32.f32 %0, %1;" : "=r"(r) : "f"(x));
    return r;
}

__device__ __forceinline__ void mma8(float* d, const uint32_t* a, const uint32_t* b) {
    asm volatile(
        "mma.sync.aligned.m16n8k8.row.col.f32.tf32.tf32.f32 "
        "{%0,%1,%2,%3},{%4,%5,%6,%7},{%8,%9},{%0,%1,%2,%3};"
        : "+f"(d[0]), "+f"(d[1]), "+f"(d[2]), "+f"(d[3])
        : "r"(a[0]), "r"(a[1]), "r"(a[2]), "r"(a[3]), "r"(b[0]), "r"(b[1]));
}

// ---------------------------------------------------------------------------
// Kernel 1: fused QKV projection (fp32 SIMT, unchanged from R1)
// ---------------------------------------------------------------------------
__global__ __launch_bounds__(256) void qkv_gemm_kernel(
    const float* __restrict__ x, const float* __restrict__ w)
{
    __shared__ float As[16][64];
    __shared__ float Bs[16][64];

    const int tid = threadIdx.x;
    const int m0 = blockIdx.y * 64;
    const int j0 = blockIdx.x * 64;
    const int lm = tid >> 2;
    const int lk = (tid & 3) * 4;
    const int ty = tid >> 4;
    const int tx = tid & 15;

    float acc[4][4];
#pragma unroll
    for (int i = 0; i < 4; i++)
#pragma unroll
        for (int j = 0; j < 4; j++) acc[i][j] = 0.f;

    for (int k0 = 0; k0 < Cq; k0 += 16) {
        float4 av = *(const float4*)&x[(size_t)(m0 + lm) * Cq + k0 + lk];
        float4 bv = *(const float4*)&w[(size_t)(j0 + lm) * Cq + k0 + lk];
        __syncthreads();
        As[lk + 0][lm] = av.x; As[lk + 1][lm] = av.y;
        As[lk + 2][lm] = av.z; As[lk + 3][lm] = av.w;
        Bs[lk + 0][lm] = bv.x; Bs[lk + 1][lm] = bv.y;
        Bs[lk + 2][lm] = bv.z; Bs[lk + 3][lm] = bv.w;
        __syncthreads();
#pragma unroll
        for (int kk = 0; kk < 16; kk++) {
            float4 a = *(float4*)&As[kk][ty * 4];
            float4 b = *(float4*)&Bs[kk][tx * 4];
            float aa[4] = {a.x, a.y, a.z, a.w};
            float bb[4] = {b.x, b.y, b.z, b.w};
#pragma unroll
            for (int i = 0; i < 4; i++)
#pragma unroll
                for (int j = 0; j < 4; j++) acc[i][j] += aa[i] * bb[j];
        }
    }

    const int jbase = j0 + tx * 4;
    const int s = jbase / Cq;
    const int h = (jbase % Cq) / Dq;
    const int d0 = jbase % Dq;
    float* dst = (s == 0) ? g_q : ((s == 1) ? g_k : g_v);

#pragma unroll
    for (int i = 0; i < 4; i++) {
        int t = m0 + ty * 4 + i;
        int b = t >> 11;
        int n = t & (Nq - 1);
        float4 v4 = make_float4(acc[i][0], acc[i][1], acc[i][2], acc[i][3]);
        *(float4*)&dst[(((size_t)b * Hq + h) * Nq + n) * Dq + d0] = v4;
    }
}

// ---------------------------------------------------------------------------
// Kernel 2: fused attention with tf32 tensor-core mma.
// One CTA = (b,h) x 16 query rows. 8 warps / 256 threads.
// Phase 1: S = (Q*scale) K^T via m16n8k8 tf32, Q split hi/lo (fp32-accurate Q).
// Softmax over the full 16x2048 fp32 strip in smem; normalized attn -> gmem.
// Phase 2: ctx = P V via m16n8k8 tf32, V split hi/lo.
// ---------------------------------------------------------------------------
#define SS_OFF 0
#define SS_SZ  (16 * SSTR)          // 32832
#define QH_OFF (SS_OFF + SS_SZ)     // 32832
#define QH_SZ  (16 * QSTR)          // 1040
#define QL_OFF (QH_OFF + QH_SZ)     // 33872
#define KS_OFF (QL_OFF + QH_SZ)     // 34912
#define KS_SZ  (128 * KSTR)         // 8704
#define SMEM_FLOATS (KS_OFF + KS_SZ)  // 43616 floats = 174464 B

__global__ __launch_bounds__(256) void attn_kernel(float* __restrict__ attnp)
{
    extern __shared__ float sm[];
    float* Ssm = sm + SS_OFF;
    float* Qh  = sm + QH_OFF;
    float* Ql  = sm + QL_OFF;
    float* Ks  = sm + KS_OFF;   // K chunk in phase 1, V chunk in phase 2

    const int tid  = threadIdx.x;
    const int lane = tid & 31;
    const int warp = tid >> 5;
    const int g    = lane >> 2;   // groupID  (0..7)
    const int t    = lane & 3;    // tid-in-group (0..3)

    const int bh = blockIdx.y;
    const int q0 = blockIdx.x * 16;
    const int b  = bh / Hq;
    const int h  = bh - b * Hq;

    const float* qptr = g_q + (size_t)bh * Nq * Dq;
    const float* kptr = g_k + (size_t)bh * Nq * Dq;
    const float* vptr = g_v + (size_t)bh * Nq * Dq;

    // ---- Q setup: load, scale, split into tf32 hi/lo ----
    {
        int r  = tid >> 4;
        int d4 = (tid & 15) * 4;
        float4 qv = *(const float4*)&qptr[(size_t)(q0 + r) * Dq + d4];
        float qa[4] = {qv.x * 0.125f, qv.y * 0.125f, qv.z * 0.125f, qv.w * 0.125f};
#pragma unroll
        for (int j = 0; j < 4; j++) {
            float hi = __uint_as_float(f2tf(qa[j]));
            float lo = __uint_as_float(f2tf(qa[j] - hi));
            Qh[r * QSTR + d4 + j] = hi;
            Ql[r * QSTR + d4 + j] = lo;
        }
    }
    __syncthreads();

    // ---- Preload Q A-fragments into registers (8 ksteps, hi+lo) ----
    uint32_t Ah[8][4], Al[8][4];
#pragma unroll
    for (int ks = 0; ks < 8; ks++) {
        int dd = ks * 8 + t;
        Ah[ks][0] = __float_as_uint(Qh[g * QSTR + dd]);
        Ah[ks][1] = __float_as_uint(Qh[(g + 8) * QSTR + dd]);
        Ah[ks][2] = __float_as_uint(Qh[g * QSTR + dd + 4]);
        Ah[ks][3] = __float_as_uint(Qh[(g + 8) * QSTR + dd + 4]);
        Al[ks][0] = __float_as_uint(Ql[g * QSTR + dd]);
        Al[ks][1] = __float_as_uint(Ql[(g + 8) * QSTR + dd]);
        Al[ks][2] = __float_as_uint(Ql[g * QSTR + dd + 4]);
        Al[ks][3] = __float_as_uint(Ql[(g + 8) * QSTR + dd + 4]);
    }

    // ---- Phase 1: scores ----
    for (int kt = 0; kt < Nq; kt += 128) {
        __syncthreads();
        // Load K chunk [128 keys][64 d] into Ks (stride KSTR)
#pragma unroll
        for (int i = 0; i < 8; i++) {
            int f = tid + i * 256;
            int key = f >> 4;
            int d4  = (f & 15) * 4;
            float4 kv = *(const float4*)&kptr[(size_t)(kt + key) * Dq + d4];
            *(float4*)&Ks[key * KSTR + d4] = kv;
        }
        __syncthreads();

#pragma unroll
        for (int nt = 0; nt < 2; nt++) {
            int key0 = (warp << 4) + (nt << 3);
            float acc[4] = {0.f, 0.f, 0.f, 0.f};
#pragma unroll
            for (int ks = 0; ks < 8; ks++) {
                uint32_t bb[2];
                bb[0] = f2tf(Ks[(key0 + g) * KSTR + ks * 8 + t]);
                bb[1] = f2tf(Ks[(key0 + g) * KSTR + ks * 8 + t + 4]);
                mma8(acc, Ah[ks], bb);
                mma8(acc, Al[ks], bb);
            }
            int col = kt + key0 + 2 * t;
            *(float2*)&Ssm[g * SSTR + col]       = make_float2(acc[0], acc[1]);
            *(float2*)&Ssm[(g + 8) * SSTR + col] = make_float2(acc[2], acc[3]);
        }
    }
    __syncthreads();

    // ---- Softmax over each row (16 threads per row) + write attn to gmem ----
    {
        const int r  = tid >> 4;
        const int gg = tid & 15;
        float mx = -1e30f;
#pragma unroll 4
        for (int i = 0; i < 32; i++) {
            float4 v = *(float4*)&Ssm[r * SSTR + gg * 4 + i * 64];
            mx = fmaxf(mx, fmaxf(fmaxf(v.x, v.y), fmaxf(v.z, v.w)));
        }
#pragma unroll
        for (int off = 8; off >= 1; off >>= 1)
            mx = fmaxf(mx, __shfl_xor_sync(0xffffffffu, mx, off, 16));

        float sum = 0.f;
#pragma unroll 4
        for (int i = 0; i < 32; i++) {
            int c = gg * 4 + i * 64;
            float4 v = *(float4*)&Ssm[r * SSTR + c];
            v.x = __expf(v.x - mx); v.y = __expf(v.y - mx);
            v.z = __expf(v.z - mx); v.w = __expf(v.w - mx);
            sum += v.x + v.y + v.z + v.w;
            *(float4*)&Ssm[r * SSTR + c] = v;
        }
#pragma unroll
        for (int off = 8; off >= 1; off >>= 1)
            sum += __shfl_xor_sync(0xffffffffu, sum, off, 16);
        float inv = 1.f / sum;

        float* aprow = attnp ? attnp + ((size_t)bh * Nq + (q0 + r)) * (size_t)Nq : (float*)0;
#pragma unroll 4
        for (int i = 0; i < 32; i++) {
            int c = gg * 4 + i * 64;
            float4 v = *(float4*)&Ssm[r * SSTR + c];
            v.x *= inv; v.y *= inv; v.z *= inv; v.w *= inv;
            *(float4*)&Ssm[r * SSTR + c] = v;
            if (aprow) *(float4*)&aprow[c] = v;
        }
    }
    __syncthreads();

    // ---- Phase 2: ctx = P V  (tf32 mma, V split hi/lo) ----
    // warp -> d-range (w&3)*16 (2 n-tiles of 8), kstep-half (w>>2)
    const int db = (warp & 3) * 16;
    const int kh = warp >> 2;

    float acc2[2][4];
#pragma unroll
    for (int n2 = 0; n2 < 2; n2++)
#pragma unroll
        for (int j = 0; j < 4; j++) acc2[n2][j] = 0.f;

    for (int vt = 0; vt < Nq; vt += 128) {
        __syncthreads();
#pragma unroll
        for (int i = 0; i < 8; i++) {
            int f = tid + i * 256;
            int key = f >> 4;
            int d4  = (f & 15) * 4;
            float4 vv = *(const float4*)&vptr[(size_t)(vt + key) * Dq + d4];
            *(float4*)&Ks[key * KSTR + d4] = vv;
        }
        __syncthreads();

#pragma unroll
        for (int ks = 0; ks < 8; ks++) {
            int kk = (kh * 8 + ks) * 8;     // key offset within chunk
            int col = vt + kk;
            uint32_t aa[4];
            aa[0] = f2tf(Ssm[g * SSTR + col + t]);
            aa[1] = f2tf(Ssm[(g + 8) * SSTR + col + t]);
            aa[2] = f2tf(Ssm[g * SSTR + col + t + 4]);
            aa[3] = f2tf(Ssm[(g + 8) * SSTR + col + t + 4]);
#pragma unroll
            for (int n2 = 0; n2 < 2; n2++) {
                int dd = db + n2 * 8 + g;
                float v0 = Ks[(kk + t) * KSTR + dd];
                float v1 = Ks[(kk + t + 4) * KSTR + dd];
                uint32_t bh0 = f2tf(v0);
                uint32_t bl0 = f2tf(v0 - __uint_as_float(bh0));
                uint32_t bh1 = f2tf(v1);
                uint32_t bl1 = f2tf(v1 - __uint_as_float(bh1));
                uint32_t bhv[2] = {bh0, bh1};
                uint32_t blv[2] = {bl0, bl1};
                mma8(acc2[n2], aa, bhv);
                mma8(acc2[n2], aa, blv);
            }
        }
    }

    // combine the two kstep-halves via smem partials (reuse Qh region)
    float* Pp = Qh;   // needs 16*64 = 1024 floats; QH_SZ = 1040
    __syncthreads();
    if (kh == 1) {
#pragma unroll
        for (int n2 = 0; n2 < 2; n2++) {
            int dc = db + n2 * 8 + 2 * t;
            *(float2*)&Pp[g * 64 + dc]       = make_float2(acc2[n2][0], acc2[n2][1]);
            *(float2*)&Pp[(g + 8) * 64 + dc] = make_float2(acc2[n2][2], acc2[n2][3]);
        }
    }
    __syncthreads();
    if (kh == 0) {
#pragma unroll
        for (int n2 = 0; n2 < 2; n2++) {
            int dc = db + n2 * 8 + 2 * t;
            float2 p0 = *(float2*)&Pp[g * 64 + dc];
            float2 p1 = *(float2*)&Pp[(g + 8) * 64 + dc];
            size_t tok0 = (size_t)b * Nq + (q0 + g);
            size_t tok1 = (size_t)b * Nq + (q0 + g + 8);
            *(float2*)&g_ctx[tok0 * Cq + h * Dq + dc] =
                make_float2(acc2[n2][0] + p0.x, acc2[n2][1] + p0.y);
            *(float2*)&g_ctx[tok1 * Cq + h * Dq + dc] =
                make_float2(acc2[n2][2] + p1.x, acc2[n2][3] + p1.y);
        }
    }
}

// ---------------------------------------------------------------------------
// Kernel 3: output projection (fp32 SIMT, unchanged from R1)
// ---------------------------------------------------------------------------
__global__ __launch_bounds__(256) void proj_gemm_kernel(
    const float* __restrict__ w, const float* __restrict__ bias,
    float* __restrict__ out)
{
    __shared__ float As[16][64];
    __shared__ float Bs[16][64];

    const int tid = threadIdx.x;
    const int m0 = blockIdx.y * 64;
    const int j0 = blockIdx.x * 64;
    const int lm = tid >> 2;
    const int lk = (tid & 3) * 4;
    const int ty = tid >> 4;
    const int tx = tid & 15;

    float acc[4][4];
#pragma unroll
    for (int i = 0; i < 4; i++)
#pragma unroll
        for (int j = 0; j < 4; j++) acc[i][j] = 0.f;

    for (int k0 = 0; k0 < Cq; k0 += 16) {
        float4 av = *(const float4*)&g_ctx[(size_t)(m0 + lm) * Cq + k0 + lk];
        float4 bv = *(const float4*)&w[(size_t)(j0 + lm) * Cq + k0 + lk];
        __syncthreads();
        As[lk + 0][lm] = av.x; As[lk + 1][lm] = av.y;
        As[lk + 2][lm] = av.z; As[lk + 3][lm] = av.w;
        Bs[lk + 0][lm] = bv.x; Bs[lk + 1][lm] = bv.y;
        Bs[lk + 2][lm] = bv.z; Bs[lk + 3][lm] = bv.w;
        __syncthreads();
#pragma unroll
        for (int kk = 0; kk < 16; kk++) {
            float4 a = *(float4*)&As[kk][ty * 4];
            float4 b4 = *(float4*)&Bs[kk][tx * 4];
            float aa[4] = {a.x, a.y, a.z, a.w};
            float bb[4] = {b4.x, b4.y, b4.z, b4.w};
#pragma unroll
            for (int i = 0; i < 4; i++)
#pragma unroll
                for (int j = 0; j < 4; j++) acc[i][j] += aa[i] * bb[j];
        }
    }

    float4 bv = *(const float4*)&bias[j0 + tx * 4];
#pragma unroll
    for (int i = 0; i < 4; i++) {
        float4 o = make_float4(acc[i][0] + bv.x, acc[i][1] + bv.y,
                               acc[i][2] + bv.z, acc[i][3] + bv.w);
        *(float4*)&out[(size_t)(m0 + ty * 4 + i) * Cq + j0 + tx * 4] = o;
    }
}

// ---------------------------------------------------------------------------
extern "C" void kernel_launch(void* const* d_in, const int* in_sizes, int n_in,
                              void* d_out, int out_size)
{
    const float* x      = (const float*)d_in[0];
    const float* w_qkv  = (const float*)d_in[1];
    const float* w_proj = (const float*)d_in[2];
    const float* b_proj = (const float*)d_in[3];

    const size_t out_elems  = (size_t)Mq * Cq;
    const size_t attn_elems = (size_t)BHq * Nq * (size_t)Nq;

    float* outp  = nullptr;
    float* attnp = nullptr;
    if ((size_t)out_size >= out_elems + attn_elems) {
        outp  = (float*)d_out;
        attnp = (float*)d_out + out_elems;
    } else if ((size_t)out_size == attn_elems) {
        attnp = (float*)d_out;
    } else {
        outp = (float*)d_out;
    }

    qkv_gemm_kernel<<<dim3(QKVq / 64, Mq / 64), 256>>>(x, w_qkv);

    static const int smem_bytes = SMEM_FLOATS * 4;   // 174464
    cudaFuncSetAttribute(attn_kernel, cudaFuncAttributeMaxDynamicSharedMemorySize,
                         smem_bytes);
    attn_kernel<<<dim3(Nq / 16, BHq), 256, smem_bytes>>>(attnp);

    if (outp) {
        proj_gemm_kernel<<<dim3(Cq / 64, Mq / 64), 256>>>(w_proj, b_proj, outp);
    }
}

// round 4
// speedup vs baseline: 2.0664x; 2.0664x over previous
#include <cuda_runtime.h>
#include <math.h>
#include <stdint.h>

#define Bq 8
#define Nq 2048
#define Cq 384
#define Hq 6
#define Dq 64
#define Mq (Bq * Nq)
#define QKVq (3 * Cq)
#define BHq (Bq * Hq)
#define LOG2E 1.4426950408889634f

__device__ float g_q[BHq * Nq * Dq];
__device__ float g_k[BHq * Nq * Dq];
__device__ float g_v[BHq * Nq * Dq];
__device__ float g_ctx[(size_t)Mq * Cq];

__device__ __forceinline__ uint32_t f2tf(float x) {
    uint32_t r;
    asm("cvt.rna.tf32.f32 %0, %1;" : "=r"(r) : "f"(x));
    return r;
}
__device__ __forceinline__ float tfv(float x) { return __uint_as_float(f2tf(x)); }
__device__ __forceinline__ float ex2(float x) {
    float r;
    asm("ex2.approx.f32 %0, %1;" : "=f"(r) : "f"(x));
    return r;
}
__device__ __forceinline__ void mma8(float* d, const uint32_t* a, const uint32_t* b) {
    asm volatile(
        "mma.sync.aligned.m16n8k8.row.col.f32.tf32.tf32.f32 "
        "{%0,%1,%2,%3},{%4,%5,%6,%7},{%8,%9},{%0,%1,%2,%3};"
        : "+f"(d[0]), "+f"(d[1]), "+f"(d[2]), "+f"(d[3])
        : "r"(a[0]), "r"(a[1]), "r"(a[2]), "r"(a[3]), "r"(b[0]), "r"(b[1]));
}
__device__ __forceinline__ void st_tf(float* d, float4 v) {
    d[0] = tfv(v.x); d[1] = tfv(v.y); d[2] = tfv(v.z); d[3] = tfv(v.w);
}

// ===========================================================================
// Kernel 1: QKV projection (fp32 SIMT, as R1)
// ===========================================================================
__global__ __launch_bounds__(256) void qkv_gemm_kernel(
    const float* __restrict__ x, const float* __restrict__ w)
{
    __shared__ float As[16][64];
    __shared__ float Bs[16][64];

    const int tid = threadIdx.x;
    const int m0 = blockIdx.y * 64, j0 = blockIdx.x * 64;
    const int lm = tid >> 2, lk = (tid & 3) * 4;
    const int ty = tid >> 4, tx = tid & 15;

    float acc[4][4];
#pragma unroll
    for (int i = 0; i < 4; i++)
#pragma unroll
        for (int j = 0; j < 4; j++) acc[i][j] = 0.f;

    for (int k0 = 0; k0 < Cq; k0 += 16) {
        float4 av = *(const float4*)&x[(size_t)(m0 + lm) * Cq + k0 + lk];
        float4 bv = *(const float4*)&w[(size_t)(j0 + lm) * Cq + k0 + lk];
        __syncthreads();
        As[lk + 0][lm] = av.x; As[lk + 1][lm] = av.y;
        As[lk + 2][lm] = av.z; As[lk + 3][lm] = av.w;
        Bs[lk + 0][lm] = bv.x; Bs[lk + 1][lm] = bv.y;
        Bs[lk + 2][lm] = bv.z; Bs[lk + 3][lm] = bv.w;
        __syncthreads();
#pragma unroll
        for (int kk = 0; kk < 16; kk++) {
            float4 a = *(float4*)&As[kk][ty * 4];
            float4 b = *(float4*)&Bs[kk][tx * 4];
            float aa[4] = {a.x, a.y, a.z, a.w};
            float bb[4] = {b.x, b.y, b.z, b.w};
#pragma unroll
            for (int i = 0; i < 4; i++)
#pragma unroll
                for (int j = 0; j < 4; j++) acc[i][j] += aa[i] * bb[j];
        }
    }

    const int jbase = j0 + tx * 4;
    const int s = jbase / Cq;
    const int h = (jbase % Cq) / Dq;
    const int d0 = jbase % Dq;
    float* dst = (s == 0) ? g_q : ((s == 1) ? g_k : g_v);
#pragma unroll
    for (int i = 0; i < 4; i++) {
        int t = m0 + ty * 4 + i;
        int b = t >> 11, n = t & (Nq - 1);
        *(float4*)&dst[(((size_t)b * Hq + h) * Nq + n) * Dq + d0] =
            make_float4(acc[i][0], acc[i][1], acc[i][2], acc[i][3]);
    }
}

// ===========================================================================
// Kernel 2: fused attention, 2-pass flash-style, tf32 mma.
// CTA = (b,h) x 256 rows; 512 threads; warp w owns rows w*16..w*16+15.
// ===========================================================================
#define KSTRD 68
#define VSTRD 72
#define A_QS_FL (256 * 64)
#define A_KB_FL (64 * KSTRD)
#define A_VB_FL (64 * VSTRD)
#define A_SMEM_FLOATS (A_QS_FL + 2 * A_KB_FL + 2 * A_VB_FL)  // 34304 fl

__global__ __launch_bounds__(512, 1) void attn_kernel(float* __restrict__ attnp)
{
    extern __shared__ float sma[];
    float* Qs = sma;                 // [256][64]
    float* Kb = sma + A_QS_FL;       // [2][64][KSTRD]
    float* Vb = Kb + 2 * A_KB_FL;    // [2][64][VSTRD]

    const int tid = threadIdx.x, lane = tid & 31, w = tid >> 5;
    const int g = lane >> 2, t = lane & 3;
    const int bh = blockIdx.y, q0 = blockIdx.x * 256;
    const int b = bh / Hq, h = bh - b * Hq;

    const float* qptr = g_q + (size_t)bh * Nq * Dq;
    const float* kptr = g_k + (size_t)bh * Nq * Dq;
    const float* vptr = g_v + (size_t)bh * Nq * Dq;

    // Q load: scaled by 0.125*log2e, tf32-rounded
    const float qsc = 0.125f * LOG2E;
#pragma unroll
    for (int i = 0; i < 8; i++) {
        int f = tid + i * 512;
        int row = f >> 4, d4 = (f & 15) * 4;
        float4 qv = *(const float4*)&qptr[(size_t)(q0 + row) * Dq + d4];
        Qs[row * 64 + d4 + 0] = tfv(qv.x * qsc);
        Qs[row * 64 + d4 + 1] = tfv(qv.y * qsc);
        Qs[row * 64 + d4 + 2] = tfv(qv.z * qsc);
        Qs[row * 64 + d4 + 3] = tfv(qv.w * qsc);
    }
    __syncthreads();

    // Q A-fragments (warp's 16 rows, 8 ksteps)
    uint32_t Ah[8][4];
    {
        int r0 = w * 16;
#pragma unroll
        for (int ks = 0; ks < 8; ks++) {
            int dd = ks * 8 + t;
            Ah[ks][0] = __float_as_uint(Qs[(r0 + g) * 64 + dd]);
            Ah[ks][1] = __float_as_uint(Qs[(r0 + g + 8) * 64 + dd]);
            Ah[ks][2] = __float_as_uint(Qs[(r0 + g) * 64 + dd + 4]);
            Ah[ks][3] = __float_as_uint(Qs[(r0 + g + 8) * 64 + dd + 4]);
        }
    }

    const int lkey = tid >> 4, ld4 = (tid & 15) * 4;

    // ================= pass 1: row sums =================
    float l0 = 0.f, l1 = 0.f;
    {
        float4 kr0 = *(const float4*)&kptr[(size_t)lkey * Dq + ld4];
        float4 kr1 = *(const float4*)&kptr[(size_t)(lkey + 32) * Dq + ld4];
        st_tf(&Kb[lkey * KSTRD + ld4], kr0);
        st_tf(&Kb[(lkey + 32) * KSTRD + ld4], kr1);

        for (int sc = 0; sc < 32; sc++) {
            if (sc < 31) {
                const float* kp = kptr + (size_t)(sc + 1) * 64 * Dq;
                kr0 = *(const float4*)&kp[(size_t)lkey * Dq + ld4];
                kr1 = *(const float4*)&kp[(size_t)(lkey + 32) * Dq + ld4];
            }
            __syncthreads();
            const float* kc = Kb + (sc & 1) * A_KB_FL;
#pragma unroll
            for (int nt = 0; nt < 8; nt++) {
                float a4[4] = {0.f, 0.f, 0.f, 0.f};
#pragma unroll
                for (int ks = 0; ks < 8; ks++) {
                    uint32_t bb[2] = {
                        __float_as_uint(kc[(nt * 8 + g) * KSTRD + ks * 8 + t]),
                        __float_as_uint(kc[(nt * 8 + g) * KSTRD + ks * 8 + t + 4])};
                    mma8(a4, Ah[ks], bb);
                }
                l0 += ex2(a4[0]) + ex2(a4[1]);
                l1 += ex2(a4[2]) + ex2(a4[3]);
            }
            if (sc < 31) {
                float* kd = Kb + ((sc + 1) & 1) * A_KB_FL;
                st_tf(&kd[lkey * KSTRD + ld4], kr0);
                st_tf(&kd[(lkey + 32) * KSTRD + ld4], kr1);
            }
        }
    }
    l0 += __shfl_xor_sync(0xffffffffu, l0, 1);
    l0 += __shfl_xor_sync(0xffffffffu, l0, 2);
    l1 += __shfl_xor_sync(0xffffffffu, l1, 1);
    l1 += __shfl_xor_sync(0xffffffffu, l1, 2);
    const float rinv0 = 1.f / l0;
    const float rinv1 = 1.f / l1;

    // ================= pass 2: attn + PV =================
    float vacc[8][4];
#pragma unroll
    for (int d = 0; d < 8; d++)
#pragma unroll
        for (int j = 0; j < 4; j++) vacc[d][j] = 0.f;

    float* aprow0 = attnp ? attnp + ((size_t)bh * Nq + (q0 + w * 16 + g)) * (size_t)Nq
                          : (float*)0;
    float* aprow1 = aprow0 ? aprow0 + 8 * (size_t)Nq : (float*)0;

    {
        float4 kr0 = *(const float4*)&kptr[(size_t)lkey * Dq + ld4];
        float4 kr1 = *(const float4*)&kptr[(size_t)(lkey + 32) * Dq + ld4];
        float4 vr0 = *(const float4*)&vptr[(size_t)lkey * Dq + ld4];
        float4 vr1 = *(const float4*)&vptr[(size_t)(lkey + 32) * Dq + ld4];
        __syncthreads();   // pass-1 reads done before overwrite
        st_tf(&Kb[lkey * KSTRD + ld4], kr0);
        st_tf(&Kb[(lkey + 32) * KSTRD + ld4], kr1);
        st_tf(&Vb[lkey * VSTRD + ld4], vr0);
        st_tf(&Vb[(lkey + 32) * VSTRD + ld4], vr1);

        const int L0 = g * 4 + (t >> 1);
        const int L1 = L0 + 2;
        const bool odd = (t & 1);

        for (int sc = 0; sc < 32; sc++) {
            if (sc < 31) {
                const float* kp = kptr + (size_t)(sc + 1) * 64 * Dq;
                const float* vp = vptr + (size_t)(sc + 1) * 64 * Dq;
                kr0 = *(const float4*)&kp[(size_t)lkey * Dq + ld4];
                kr1 = *(const float4*)&kp[(size_t)(lkey + 32) * Dq + ld4];
                vr0 = *(const float4*)&vp[(size_t)lkey * Dq + ld4];
                vr1 = *(const float4*)&vp[(size_t)(lkey + 32) * Dq + ld4];
            }
            __syncthreads();
            const float* kc = Kb + (sc & 1) * A_KB_FL;
            const float* vc = Vb + (sc & 1) * A_VB_FL;

#pragma unroll
            for (int nt = 0; nt < 8; nt++) {
                float a4[4] = {0.f, 0.f, 0.f, 0.f};
#pragma unroll
                for (int ks = 0; ks < 8; ks++) {
                    uint32_t bb[2] = {
                        __float_as_uint(kc[(nt * 8 + g) * KSTRD + ks * 8 + t]),
                        __float_as_uint(kc[(nt * 8 + g) * KSTRD + ks * 8 + t + 4])};
                    mma8(a4, Ah[ks], bb);
                }
                float p0 = ex2(a4[0]) * rinv0;
                float p1 = ex2(a4[1]) * rinv0;
                float p2 = ex2(a4[2]) * rinv1;
                float p3 = ex2(a4[3]) * rinv1;
                int col = sc * 64 + nt * 8 + 2 * t;
                if (aprow0) {
                    *(float2*)&aprow0[col] = make_float2(p0, p1);
                    *(float2*)&aprow1[col] = make_float2(p2, p3);
                }
                // shuffle-transpose C-frag (rows g/g+8, cols 2t,2t+1)
                // -> A-frag (rows g/g+8, key-cols t, t+4)
                float x0 = __shfl_sync(0xffffffffu, p0, L0);
                float y0 = __shfl_sync(0xffffffffu, p1, L0);
                float x1 = __shfl_sync(0xffffffffu, p2, L0);
                float y1 = __shfl_sync(0xffffffffu, p3, L0);
                float x2 = __shfl_sync(0xffffffffu, p0, L1);
                float y2 = __shfl_sync(0xffffffffu, p1, L1);
                float x3 = __shfl_sync(0xffffffffu, p2, L1);
                float y3 = __shfl_sync(0xffffffffu, p3, L1);
                uint32_t af[4];
                af[0] = f2tf(odd ? y0 : x0);
                af[1] = f2tf(odd ? y1 : x1);
                af[2] = f2tf(odd ? y2 : x2);
                af[3] = f2tf(odd ? y3 : x3);
#pragma unroll
                for (int nt2 = 0; nt2 < 8; nt2++) {
                    uint32_t bb2[2] = {
                        __float_as_uint(vc[(nt * 8 + t) * VSTRD + nt2 * 8 + g]),
                        __float_as_uint(vc[(nt * 8 + t + 4) * VSTRD + nt2 * 8 + g])};
                    mma8(vacc[nt2], af, bb2);
                }
            }
            if (sc < 31) {
                float* kd = Kb + ((sc + 1) & 1) * A_KB_FL;
                float* vd = Vb + ((sc + 1) & 1) * A_VB_FL;
                st_tf(&kd[lkey * KSTRD + ld4], kr0);
                st_tf(&kd[(lkey + 32) * KSTRD + ld4], kr1);
                st_tf(&vd[lkey * VSTRD + ld4], vr0);
                st_tf(&vd[(lkey + 32) * VSTRD + ld4], vr1);
            }
        }
    }

    // write ctx
    {
        size_t tok0 = (size_t)b * Nq + (q0 + w * 16 + g);
        size_t tok1 = tok0 + 8;
#pragma unroll
        for (int nt2 = 0; nt2 < 8; nt2++) {
            int dc = h * Dq + nt2 * 8 + 2 * t;
            *(float2*)&g_ctx[tok0 * Cq + dc] = make_float2(vacc[nt2][0], vacc[nt2][1]);
            *(float2*)&g_ctx[tok1 * Cq + dc] = make_float2(vacc[nt2][2], vacc[nt2][3]);
        }
    }
}

// ===========================================================================
// Kernel 3: output projection (fp32 SIMT, as R1)
// ===========================================================================
__global__ __launch_bounds__(256) void proj_gemm_kernel(
    const float* __restrict__ w, const float* __restrict__ bias,
    float* __restrict__ out)
{
    __shared__ float As[16][64];
    __shared__ float Bs[16][64];

    const int tid = threadIdx.x;
    const int m0 = blockIdx.y * 64, j0 = blockIdx.x * 64;
    const int lm = tid >> 2, lk = (tid & 3) * 4;
    const int ty = tid >> 4, tx = tid & 15;

    float acc[4][4];
#pragma unroll
    for (int i = 0; i < 4; i++)
#pragma unroll
        for (int j = 0; j < 4; j++) acc[i][j] = 0.f;

    for (int k0 = 0; k0 < Cq; k0 += 16) {
        float4 av = *(const float4*)&g_ctx[(size_t)(m0 + lm) * Cq + k0 + lk];
        float4 bv = *(const float4*)&w[(size_t)(j0 + lm) * Cq + k0 + lk];
        __syncthreads();
        As[lk + 0][lm] = av.x; As[lk + 1][lm] = av.y;
        As[lk + 2][lm] = av.z; As[lk + 3][lm] = av.w;
        Bs[lk + 0][lm] = bv.x; Bs[lk + 1][lm] = bv.y;
        Bs[lk + 2][lm] = bv.z; Bs[lk + 3][lm] = bv.w;
        __syncthreads();
#pragma unroll
        for (int kk = 0; kk < 16; kk++) {
            float4 a = *(float4*)&As[kk][ty * 4];
            float4 b4 = *(float4*)&Bs[kk][tx * 4];
            float aa[4] = {a.x, a.y, a.z, a.w};
            float bb[4] = {b4.x, b4.y, b4.z, b4.w};
#pragma unroll
            for (int i = 0; i < 4; i++)
#pragma unroll
                for (int j = 0; j < 4; j++) acc[i][j] += aa[i] * bb[j];
        }
    }

    float4 bv = *(const float4*)&bias[j0 + tx * 4];
#pragma unroll
    for (int i = 0; i < 4; i++) {
        *(float4*)&out[(size_t)(m0 + ty * 4 + i) * Cq + j0 + tx * 4] =
            make_float4(acc[i][0] + bv.x, acc[i][1] + bv.y,
                        acc[i][2] + bv.z, acc[i][3] + bv.w);
    }
}

// ===========================================================================
extern "C" void kernel_launch(void* const* d_in, const int* in_sizes, int n_in,
                              void* d_out, int out_size)
{
    const float* x      = (const float*)d_in[0];
    const float* w_qkv  = (const float*)d_in[1];
    const float* w_proj = (const float*)d_in[2];
    const float* b_proj = (const float*)d_in[3];

    const size_t out_elems  = (size_t)Mq * Cq;
    const size_t attn_elems = (size_t)BHq * Nq * (size_t)Nq;

    float* outp  = nullptr;
    float* attnp = nullptr;
    if ((size_t)out_size >= out_elems + attn_elems) {
        outp  = (float*)d_out;
        attnp = (float*)d_out + out_elems;
    } else if ((size_t)out_size == attn_elems) {
        attnp = (float*)d_out;
    } else {
        outp = (float*)d_out;
    }

    qkv_gemm_kernel<<<dim3(QKVq / 64, Mq / 64), 256>>>(x, w_qkv);

    static const int asm_bytes = A_SMEM_FLOATS * 4;   // 137216
    cudaFuncSetAttribute(attn_kernel, cudaFuncAttributeMaxDynamicSharedMemorySize,
                         asm_bytes);
    attn_kernel<<<dim3(Nq / 256, BHq), 512, asm_bytes>>>(attnp);

    if (outp) {
        proj_gemm_kernel<<<dim3(Cq / 64, Mq / 64), 256>>>(w_proj, b_proj, outp);
    }
}

// round 5
// speedup vs baseline: 2.9284x; 1.4172x over previous
#include <cuda_runtime.h>
#include <math.h>
#include <stdint.h>

#define Bq 8
#define Nq 2048
#define Cq 384
#define Hq 6
#define Dq 64
#define Mq (Bq * Nq)
#define QKVq (3 * Cq)
#define BHq (Bq * Hq)
#define LOG2E 1.4426950408889634f

__device__ float g_q[BHq * Nq * Dq];
__device__ float g_k[BHq * Nq * Dq];
__device__ float g_v[BHq * Nq * Dq];
__device__ float g_ctx[(size_t)Mq * Cq];

__device__ __forceinline__ uint32_t f2tf(float x) {
    uint32_t r;
    asm("cvt.rna.tf32.f32 %0, %1;" : "=r"(r) : "f"(x));
    return r;
}
__device__ __forceinline__ float tfv(float x) { return __uint_as_float(f2tf(x)); }
__device__ __forceinline__ float ex2(float x) {
    float r;
    asm("ex2.approx.f32 %0, %1;" : "=f"(r) : "f"(x));
    return r;
}
__device__ __forceinline__ void mma8(float* d, const uint32_t* a, const uint32_t* b) {
    asm volatile(
        "mma.sync.aligned.m16n8k8.row.col.f32.tf32.tf32.f32 "
        "{%0,%1,%2,%3},{%4,%5,%6,%7},{%8,%9},{%0,%1,%2,%3};"
        : "+f"(d[0]), "+f"(d[1]), "+f"(d[2]), "+f"(d[3])
        : "r"(a[0]), "r"(a[1]), "r"(a[2]), "r"(a[3]), "r"(b[0]), "r"(b[1]));
}
__device__ __forceinline__ void st_tf(float* d, float4 v) {
    d[0] = tfv(v.x); d[1] = tfv(v.y); d[2] = tfv(v.z); d[3] = tfv(v.w);
}

// ===========================================================================
// Shared GEMM core: out[M,N] tiles of x[M,K] @ w[N,K]^T, tf32 mma,
// weights split hi/lo (exact), x single tf32.
// CTA: 128(M) x 128(N), 256 threads, K-chunk 16, double buffered.
// ===========================================================================
#define GSTR 20
#define G_CH_FL (128 * GSTR)              // 2560 floats per (buf, matrix)
#define G_SMEM_FLOATS (6 * G_CH_FL)       // 15360 fl = 61440 B

// KCH chunks of 16 = K total. Epilogue via functor-style macro duplication.
template <int KCHUNKS>
__device__ __forceinline__ void gemm_core(
    const float* __restrict__ x, const float* __restrict__ w,
    int m0, int j0, int K, float* smg, float acc[2][8][4])
{
    float* Xs = smg;
    float* Wh = smg + 2 * G_CH_FL;
    float* Wl = smg + 4 * G_CH_FL;

    const int tid = threadIdx.x, lane = tid & 31, wp = tid >> 5;
    const int g = lane >> 2, t = lane & 3;
    const int wm = wp & 3, wn = wp >> 2;

#pragma unroll
    for (int a = 0; a < 2; a++)
#pragma unroll
        for (int b = 0; b < 8; b++)
#pragma unroll
            for (int c = 0; c < 4; c++) acc[a][b][c] = 0.f;

    float4 xr[2], wr[2];
    // loader mapping: 512 float4s per matrix per chunk; 2 per thread
#pragma unroll
    for (int i = 0; i < 2; i++) {
        int f = tid + i * 256;
        int row = f >> 2, c4 = (f & 3) * 4;
        xr[i] = *(const float4*)&x[(size_t)(m0 + row) * K + c4];
        wr[i] = *(const float4*)&w[(size_t)(j0 + row) * K + c4];
    }
#pragma unroll
    for (int i = 0; i < 2; i++) {
        int f = tid + i * 256;
        int row = f >> 2, c4 = (f & 3) * 4;
        st_tf(&Xs[row * GSTR + c4], xr[i]);
        float wv[4] = {wr[i].x, wr[i].y, wr[i].z, wr[i].w};
#pragma unroll
        for (int j = 0; j < 4; j++) {
            float hi = tfv(wv[j]);
            Wh[row * GSTR + c4 + j] = hi;
            Wl[row * GSTR + c4 + j] = tfv(wv[j] - hi);
        }
    }

    for (int ch = 0; ch < KCHUNKS; ch++) {
        if (ch < KCHUNKS - 1) {
            int k0 = (ch + 1) * 16;
#pragma unroll
            for (int i = 0; i < 2; i++) {
                int f = tid + i * 256;
                int row = f >> 2, c4 = (f & 3) * 4;
                xr[i] = *(const float4*)&x[(size_t)(m0 + row) * K + k0 + c4];
                wr[i] = *(const float4*)&w[(size_t)(j0 + row) * K + k0 + c4];
            }
        }
        __syncthreads();
        const float* Xc = Xs + (ch & 1) * G_CH_FL;
        const float* Whc = Wh + (ch & 1) * G_CH_FL;
        const float* Wlc = Wl + (ch & 1) * G_CH_FL;

#pragma unroll
        for (int ks = 0; ks < 2; ks++) {
            uint32_t af[2][4];
#pragma unroll
            for (int mt = 0; mt < 2; mt++) {
                int r = wm * 32 + mt * 16;
                af[mt][0] = __float_as_uint(Xc[(r + g) * GSTR + ks * 8 + t]);
                af[mt][1] = __float_as_uint(Xc[(r + g + 8) * GSTR + ks * 8 + t]);
                af[mt][2] = __float_as_uint(Xc[(r + g) * GSTR + ks * 8 + t + 4]);
                af[mt][3] = __float_as_uint(Xc[(r + g + 8) * GSTR + ks * 8 + t + 4]);
            }
#pragma unroll
            for (int nt = 0; nt < 8; nt++) {
                int c = wn * 64 + nt * 8;
                uint32_t bh2[2] = {
                    __float_as_uint(Whc[(c + g) * GSTR + ks * 8 + t]),
                    __float_as_uint(Whc[(c + g) * GSTR + ks * 8 + t + 4])};
                uint32_t bl2[2] = {
                    __float_as_uint(Wlc[(c + g) * GSTR + ks * 8 + t]),
                    __float_as_uint(Wlc[(c + g) * GSTR + ks * 8 + t + 4])};
                mma8(acc[0][nt], af[0], bh2);
                mma8(acc[0][nt], af[0], bl2);
                mma8(acc[1][nt], af[1], bh2);
                mma8(acc[1][nt], af[1], bl2);
            }
        }
        if (ch < KCHUNKS - 1) {
            float* Xd = Xs + ((ch + 1) & 1) * G_CH_FL;
            float* Whd = Wh + ((ch + 1) & 1) * G_CH_FL;
            float* Wld = Wl + ((ch + 1) & 1) * G_CH_FL;
#pragma unroll
            for (int i = 0; i < 2; i++) {
                int f = tid + i * 256;
                int row = f >> 2, c4 = (f & 3) * 4;
                st_tf(&Xd[row * GSTR + c4], xr[i]);
                float wv[4] = {wr[i].x, wr[i].y, wr[i].z, wr[i].w};
#pragma unroll
                for (int j = 0; j < 4; j++) {
                    float hi = tfv(wv[j]);
                    Whd[row * GSTR + c4 + j] = hi;
                    Wld[row * GSTR + c4 + j] = tfv(wv[j] - hi);
                }
            }
        }
    }
}

// ===========================================================================
// Kernel 1: QKV projection, epilogue scatters to g_q/g_k/g_v.
// ===========================================================================
__global__ __launch_bounds__(256, 2) void qkv_gemm_kernel(
    const float* __restrict__ x, const float* __restrict__ wq)
{
    extern __shared__ float smg[];
    float acc[2][8][4];
    const int m0 = blockIdx.y * 128, j0 = blockIdx.x * 128;
    gemm_core<24>(x, wq, m0, j0, Cq, smg, acc);

    const int tid = threadIdx.x, lane = tid & 31, wp = tid >> 5;
    const int g = lane >> 2, t = lane & 3;
    const int wm = wp & 3, wn = wp >> 2;

#pragma unroll
    for (int nt = 0; nt < 8; nt++) {
        int j = j0 + wn * 64 + nt * 8 + 2 * t;
        int s = j / Cq;
        int jj = j - s * Cq;
        int h = jj >> 6, d = jj & 63;
        float* dst = (s == 0) ? g_q : ((s == 1) ? g_k : g_v);
#pragma unroll
        for (int mt = 0; mt < 2; mt++) {
            int m = m0 + wm * 32 + mt * 16 + g;
            int bb = m >> 11, nn = m & (Nq - 1);
            *(float2*)&dst[(((size_t)bb * Hq + h) * Nq + nn) * Dq + d] =
                make_float2(acc[mt][nt][0], acc[mt][nt][1]);
            m += 8; bb = m >> 11; nn = m & (Nq - 1);
            *(float2*)&dst[(((size_t)bb * Hq + h) * Nq + nn) * Dq + d] =
                make_float2(acc[mt][nt][2], acc[mt][nt][3]);
        }
    }
}

// ===========================================================================
// Kernel 1b: output projection, epilogue adds bias, writes out.
// ===========================================================================
__global__ __launch_bounds__(256, 2) void proj_gemm_kernel(
    const float* __restrict__ w, const float* __restrict__ bias,
    float* __restrict__ out)
{
    extern __shared__ float smg[];
    float acc[2][8][4];
    const int m0 = blockIdx.y * 128, j0 = blockIdx.x * 128;
    gemm_core<24>(g_ctx, w, m0, j0, Cq, smg, acc);

    const int tid = threadIdx.x, lane = tid & 31, wp = tid >> 5;
    const int g = lane >> 2, t = lane & 3;
    const int wm = wp & 3, wn = wp >> 2;

#pragma unroll
    for (int nt = 0; nt < 8; nt++) {
        int j = j0 + wn * 64 + nt * 8 + 2 * t;
        float2 bv = *(const float2*)&bias[j];
#pragma unroll
        for (int mt = 0; mt < 2; mt++) {
            int m = m0 + wm * 32 + mt * 16 + g;
            *(float2*)&out[(size_t)m * Cq + j] =
                make_float2(acc[mt][nt][0] + bv.x, acc[mt][nt][1] + bv.y);
            *(float2*)&out[(size_t)(m + 8) * Cq + j] =
                make_float2(acc[mt][nt][2] + bv.x, acc[mt][nt][3] + bv.y);
        }
    }
}

// ===========================================================================
// Kernel 2: fused attention, 2-pass flash-style, tf32 mma (as R4).
// ===========================================================================
#define KSTRD 68
#define VSTRD 72
#define A_QS_FL (256 * 64)
#define A_KB_FL (64 * KSTRD)
#define A_VB_FL (64 * VSTRD)
#define A_SMEM_FLOATS (A_QS_FL + 2 * A_KB_FL + 2 * A_VB_FL)

__global__ __launch_bounds__(512, 1) void attn_kernel(float* __restrict__ attnp)
{
    extern __shared__ float sma[];
    float* Qs = sma;
    float* Kb = sma + A_QS_FL;
    float* Vb = Kb + 2 * A_KB_FL;

    const int tid = threadIdx.x, lane = tid & 31, w = tid >> 5;
    const int g = lane >> 2, t = lane & 3;
    const int bh = blockIdx.y, q0 = blockIdx.x * 256;
    const int b = bh / Hq, h = bh - b * Hq;

    const float* qptr = g_q + (size_t)bh * Nq * Dq;
    const float* kptr = g_k + (size_t)bh * Nq * Dq;
    const float* vptr = g_v + (size_t)bh * Nq * Dq;

    const float qsc = 0.125f * LOG2E;
#pragma unroll
    for (int i = 0; i < 8; i++) {
        int f = tid + i * 512;
        int row = f >> 4, d4 = (f & 15) * 4;
        float4 qv = *(const float4*)&qptr[(size_t)(q0 + row) * Dq + d4];
        Qs[row * 64 + d4 + 0] = tfv(qv.x * qsc);
        Qs[row * 64 + d4 + 1] = tfv(qv.y * qsc);
        Qs[row * 64 + d4 + 2] = tfv(qv.z * qsc);
        Qs[row * 64 + d4 + 3] = tfv(qv.w * qsc);
    }
    __syncthreads();

    uint32_t Ah[8][4];
    {
        int r0 = w * 16;
#pragma unroll
        for (int ks = 0; ks < 8; ks++) {
            int dd = ks * 8 + t;
            Ah[ks][0] = __float_as_uint(Qs[(r0 + g) * 64 + dd]);
            Ah[ks][1] = __float_as_uint(Qs[(r0 + g + 8) * 64 + dd]);
            Ah[ks][2] = __float_as_uint(Qs[(r0 + g) * 64 + dd + 4]);
            Ah[ks][3] = __float_as_uint(Qs[(r0 + g + 8) * 64 + dd + 4]);
        }
    }

    const int lkey = tid >> 4, ld4 = (tid & 15) * 4;

    // pass 1
    float l0 = 0.f, l1 = 0.f;
    {
        float4 kr0 = *(const float4*)&kptr[(size_t)lkey * Dq + ld4];
        float4 kr1 = *(const float4*)&kptr[(size_t)(lkey + 32) * Dq + ld4];
        st_tf(&Kb[lkey * KSTRD + ld4], kr0);
        st_tf(&Kb[(lkey + 32) * KSTRD + ld4], kr1);

        for (int sc = 0; sc < 32; sc++) {
            if (sc < 31) {
                const float* kp = kptr + (size_t)(sc + 1) * 64 * Dq;
                kr0 = *(const float4*)&kp[(size_t)lkey * Dq + ld4];
                kr1 = *(const float4*)&kp[(size_t)(lkey + 32) * Dq + ld4];
            }
            __syncthreads();
            const float* kc = Kb + (sc & 1) * A_KB_FL;
#pragma unroll
            for (int nt = 0; nt < 8; nt++) {
                float a4[4] = {0.f, 0.f, 0.f, 0.f};
#pragma unroll
                for (int ks = 0; ks < 8; ks++) {
                    uint32_t bb[2] = {
                        __float_as_uint(kc[(nt * 8 + g) * KSTRD + ks * 8 + t]),
                        __float_as_uint(kc[(nt * 8 + g) * KSTRD + ks * 8 + t + 4])};
                    mma8(a4, Ah[ks], bb);
                }
                l0 += ex2(a4[0]) + ex2(a4[1]);
                l1 += ex2(a4[2]) + ex2(a4[3]);
            }
            if (sc < 31) {
                float* kd = Kb + ((sc + 1) & 1) * A_KB_FL;
                st_tf(&kd[lkey * KSTRD + ld4], kr0);
                st_tf(&kd[(lkey + 32) * KSTRD + ld4], kr1);
            }
        }
    }
    l0 += __shfl_xor_sync(0xffffffffu, l0, 1);
    l0 += __shfl_xor_sync(0xffffffffu, l0, 2);
    l1 += __shfl_xor_sync(0xffffffffu, l1, 1);
    l1 += __shfl_xor_sync(0xffffffffu, l1, 2);
    const float rinv0 = 1.f / l0;
    const float rinv1 = 1.f / l1;

    // pass 2
    float vacc[8][4];
#pragma unroll
    for (int d = 0; d < 8; d++)
#pragma unroll
        for (int j = 0; j < 4; j++) vacc[d][j] = 0.f;

    float* aprow0 = attnp ? attnp + ((size_t)bh * Nq + (q0 + w * 16 + g)) * (size_t)Nq
                          : (float*)0;
    float* aprow1 = aprow0 ? aprow0 + 8 * (size_t)Nq : (float*)0;

    {
        float4 kr0 = *(const float4*)&kptr[(size_t)lkey * Dq + ld4];
        float4 kr1 = *(const float4*)&kptr[(size_t)(lkey + 32) * Dq + ld4];
        float4 vr0 = *(const float4*)&vptr[(size_t)lkey * Dq + ld4];
        float4 vr1 = *(const float4*)&vptr[(size_t)(lkey + 32) * Dq + ld4];
        __syncthreads();
        st_tf(&Kb[lkey * KSTRD + ld4], kr0);
        st_tf(&Kb[(lkey + 32) * KSTRD + ld4], kr1);
        st_tf(&Vb[lkey * VSTRD + ld4], vr0);
        st_tf(&Vb[(lkey + 32) * VSTRD + ld4], vr1);

        const int L0 = g * 4 + (t >> 1);
        const int L1 = L0 + 2;
        const bool odd = (t & 1);

        for (int sc = 0; sc < 32; sc++) {
            if (sc < 31) {
                const float* kp = kptr + (size_t)(sc + 1) * 64 * Dq;
                const float* vp = vptr + (size_t)(sc + 1) * 64 * Dq;
                kr0 = *(const float4*)&kp[(size_t)lkey * Dq + ld4];
                kr1 = *(const float4*)&kp[(size_t)(lkey + 32) * Dq + ld4];
                vr0 = *(const float4*)&vp[(size_t)lkey * Dq + ld4];
                vr1 = *(const float4*)&vp[(size_t)(lkey + 32) * Dq + ld4];
            }
            __syncthreads();
            const float* kc = Kb + (sc & 1) * A_KB_FL;
            const float* vc = Vb + (sc & 1) * A_VB_FL;

#pragma unroll
            for (int nt = 0; nt < 8; nt++) {
                float a4[4] = {0.f, 0.f, 0.f, 0.f};
#pragma unroll
                for (int ks = 0; ks < 8; ks++) {
                    uint32_t bb[2] = {
                        __float_as_uint(kc[(nt * 8 + g) * KSTRD + ks * 8 + t]),
                        __float_as_uint(kc[(nt * 8 + g) * KSTRD + ks * 8 + t + 4])};
                    mma8(a4, Ah[ks], bb);
                }
                float p0 = ex2(a4[0]) * rinv0;
                float p1 = ex2(a4[1]) * rinv0;
                float p2 = ex2(a4[2]) * rinv1;
                float p3 = ex2(a4[3]) * rinv1;
                int col = sc * 64 + nt * 8 + 2 * t;
                if (aprow0) {
                    *(float2*)&aprow0[col] = make_float2(p0, p1);
                    *(float2*)&aprow1[col] = make_float2(p2, p3);
                }
                float x0 = __shfl_sync(0xffffffffu, p0, L0);
                float y0 = __shfl_sync(0xffffffffu, p1, L0);
                float x1 = __shfl_sync(0xffffffffu, p2, L0);
                float y1 = __shfl_sync(0xffffffffu, p3, L0);
                float x2 = __shfl_sync(0xffffffffu, p0, L1);
                float y2 = __shfl_sync(0xffffffffu, p1, L1);
                float x3 = __shfl_sync(0xffffffffu, p2, L1);
                float y3 = __shfl_sync(0xffffffffu, p3, L1);
                uint32_t af[4];
                af[0] = f2tf(odd ? y0 : x0);
                af[1] = f2tf(odd ? y1 : x1);
                af[2] = f2tf(odd ? y2 : x2);
                af[3] = f2tf(odd ? y3 : x3);
#pragma unroll
                for (int nt2 = 0; nt2 < 8; nt2++) {
                    uint32_t bb2[2] = {
                        __float_as_uint(vc[(nt * 8 + t) * VSTRD + nt2 * 8 + g]),
                        __float_as_uint(vc[(nt * 8 + t + 4) * VSTRD + nt2 * 8 + g])};
                    mma8(vacc[nt2], af, bb2);
                }
            }
            if (sc < 31) {
                float* kd = Kb + ((sc + 1) & 1) * A_KB_FL;
                float* vd = Vb + ((sc + 1) & 1) * A_VB_FL;
                st_tf(&kd[lkey * KSTRD + ld4], kr0);
                st_tf(&kd[(lkey + 32) * KSTRD + ld4], kr1);
                st_tf(&vd[lkey * VSTRD + ld4], vr0);
                st_tf(&vd[(lkey + 32) * VSTRD + ld4], vr1);
            }
        }
    }

    {
        size_t tok0 = (size_t)b * Nq + (q0 + w * 16 + g);
        size_t tok1 = tok0 + 8;
#pragma unroll
        for (int nt2 = 0; nt2 < 8; nt2++) {
            int dc = h * Dq + nt2 * 8 + 2 * t;
            *(float2*)&g_ctx[tok0 * Cq + dc] = make_float2(vacc[nt2][0], vacc[nt2][1]);
            *(float2*)&g_ctx[tok1 * Cq + dc] = make_float2(vacc[nt2][2], vacc[nt2][3]);
        }
    }
}

// ===========================================================================
extern "C" void kernel_launch(void* const* d_in, const int* in_sizes, int n_in,
                              void* d_out, int out_size)
{
    const float* x      = (const float*)d_in[0];
    const float* w_qkv  = (const float*)d_in[1];
    const float* w_proj = (const float*)d_in[2];
    const float* b_proj = (const float*)d_in[3];

    const size_t out_elems  = (size_t)Mq * Cq;
    const size_t attn_elems = (size_t)BHq * Nq * (size_t)Nq;

    float* outp  = nullptr;
    float* attnp = nullptr;
    if ((size_t)out_size >= out_elems + attn_elems) {
        outp  = (float*)d_out;
        attnp = (float*)d_out + out_elems;
    } else if ((size_t)out_size == attn_elems) {
        attnp = (float*)d_out;
    } else {
        outp = (float*)d_out;
    }

    static const int gsm_bytes = G_SMEM_FLOATS * 4;   // 61440
    cudaFuncSetAttribute(qkv_gemm_kernel, cudaFuncAttributeMaxDynamicSharedMemorySize,
                         gsm_bytes);
    cudaFuncSetAttribute(proj_gemm_kernel, cudaFuncAttributeMaxDynamicSharedMemorySize,
                         gsm_bytes);

    qkv_gemm_kernel<<<dim3(QKVq / 128, Mq / 128), 256, gsm_bytes>>>(x, w_qkv);

    static const int asm_bytes = A_SMEM_FLOATS * 4;   // 137216
    cudaFuncSetAttribute(attn_kernel, cudaFuncAttributeMaxDynamicSharedMemorySize,
                         asm_bytes);
    attn_kernel<<<dim3(Nq / 256, BHq), 512, asm_bytes>>>(attnp);

    if (outp) {
        proj_gemm_kernel<<<dim3(Cq / 128, Mq / 128), 256, gsm_bytes>>>(w_proj, b_proj, outp);
    }
}